// round 3
// baseline (speedup 1.0000x reference)
#include <cuda_runtime.h>
#include <cstdint>

#define BT 1024
#define NB 4096

typedef unsigned long long u64;

__device__ __forceinline__ u64 pk2(float lo, float hi) {
    u64 r; asm("mov.b64 %0, {%1,%2};" : "=l"(r) : "f"(lo), "f"(hi)); return r;
}
__device__ __forceinline__ u64 dup2(float v) { return pk2(v, v); }
__device__ __forceinline__ void unpk2(u64 p, float& lo, float& hi) {
    asm("mov.b64 {%0,%1}, %2;" : "=f"(lo), "=f"(hi) : "l"(p));
}
__device__ __forceinline__ u64 ffma2(u64 a, u64 b, u64 c) {
    u64 d; asm("fma.rn.f32x2 %0, %1, %2, %3;" : "=l"(d) : "l"(a), "l"(b), "l"(c)); return d;
}
__device__ __forceinline__ u64 fadd2(u64 a, u64 b) {
    u64 d; asm("add.rn.f32x2 %0, %1, %2;" : "=l"(d) : "l"(a), "l"(b)); return d;
}
__device__ __forceinline__ float ex2f(float x) {
    float y; asm("ex2.approx.f32 %0, %1;" : "=f"(y) : "f"(x)); return y;
}
__device__ __forceinline__ float rcpf(float x) {
    float y; asm("rcp.approx.f32 %0, %1;" : "=f"(y) : "f"(x)); return y;
}

// Packed per-thread weights for one LSTM cell: thread owns hidden unit j.
// wif[k] = (W_i[j][k]*(-log2e), W_f[j][k]*(-log2e)), wgo[k] = (W_g[j][k]*(2log2e), W_o[j][k]*(-log2e))
// k = 0..5 input-part, 6..11 hidden-part. Biases pre-folded identically.
struct LW {
    u64 wif[12];
    u64 wgo[12];
    u64 bif, bgo;
};

// One LSTM cell step for this thread's hidden unit.
// A[0..5]  = first 6 inputs (dup-packed), Bv[0..5] = prev hidden (dup-packed).
// Activation fusion (weights pre-scaled so EX2 args are direct):
//   i*g = (Eg-1) * rcp((Eg+1)*(Ei+1));  f*c = c * rcp(Ef+1)
//   h   = (Ec-1) * rcp((Ec+1)*(Eo+1)),  Ec = ex2(min(2*log2e*c, 100))
// => 5 EX2 + 3 RCP per cell (MUFU is the binding pipe chip-wide).
__device__ __forceinline__ void lstm_cell(const LW& w, const u64* A, const u64* Bv,
                                          float& c, float& h)
{
    u64 aif  = w.bif, ago = w.bgo;
    u64 aif2 = 0ull,  ago2 = 0ull;   // second accumulation chain (halves dep depth)
#pragma unroll
    for (int k = 0; k < 6; ++k) {
        aif  = ffma2(w.wif[k],     A[k],  aif);
        ago  = ffma2(w.wgo[k],     A[k],  ago);
        aif2 = ffma2(w.wif[k + 6], Bv[k], aif2);
        ago2 = ffma2(w.wgo[k + 6], Bv[k], ago2);
    }
    aif = fadd2(aif, aif2);
    ago = fadd2(ago, ago2);
    float zi, zf, zg, zo;
    unpk2(aif, zi, zf);
    unpk2(ago, zg, zo);
    float Ei = ex2f(zi), Ef = ex2f(zf), Eg = ex2f(zg), Eo = ex2f(zo);
    float ig = (Eg - 1.0f) * rcpf((Eg + 1.0f) * (Ei + 1.0f));
    c = fmaf(c, rcpf(Ef + 1.0f), ig);
    float zc = fminf(c * 2.8853900817779268f, 100.0f);  // clamp: keep rcp product finite
    float Ec = ex2f(zc);
    h = (Ec - 1.0f) * rcpf((Ec + 1.0f) * (Eo + 1.0f));
}

__global__ void __launch_bounds__(64, 1)
lstm2_kernel(const float* __restrict__ x,
             const float* __restrict__ wih0, const float* __restrict__ whh0,
             const float* __restrict__ bih0, const float* __restrict__ bhh0,
             const float* __restrict__ wih1, const float* __restrict__ whh1,
             const float* __restrict__ bih1, const float* __restrict__ bhh1,
             float* __restrict__ out)
{
    const int lane = threadIdx.x & 31;
    const int gw   = blockIdx.x * (blockDim.x >> 5) + (threadIdx.x >> 5);
    const int j    = lane % 6;     // hidden unit
    const int e    = lane / 6;     // element slot within warp (0..4 active)
    int b = gw * 5 + e;
    const bool active = (e < 5) && (b < NB);
    if (b >= NB) b = NB - 1;       // clamp for safe (dead) loads
    const int base = lane - j;     // first lane of this element's group

    const float SSIG = -1.4426950408889634f;   // -log2(e)
    const float SG   =  2.8853900817779268f;   //  2*log2(e)

    // ---- pre-fold weights into packed registers (depends only on j) ----
    LW W0, W1;
#pragma unroll
    for (int k = 0; k < 12; ++k) {
        const float* Wa = (k < 6) ? wih0 : whh0;
        const float* Wb = (k < 6) ? wih1 : whh1;
        const int kk = (k < 6) ? k : k - 6;
        W0.wif[k] = pk2(Wa[(j     ) * 6 + kk] * SSIG, Wa[(j +  6) * 6 + kk] * SSIG);
        W0.wgo[k] = pk2(Wa[(j + 12) * 6 + kk] * SG,   Wa[(j + 18) * 6 + kk] * SSIG);
        W1.wif[k] = pk2(Wb[(j     ) * 6 + kk] * SSIG, Wb[(j +  6) * 6 + kk] * SSIG);
        W1.wgo[k] = pk2(Wb[(j + 12) * 6 + kk] * SG,   Wb[(j + 18) * 6 + kk] * SSIG);
    }
    W0.bif = pk2((bih0[j     ] + bhh0[j     ]) * SSIG, (bih0[j +  6] + bhh0[j +  6]) * SSIG);
    W0.bgo = pk2((bih0[j + 12] + bhh0[j + 12]) * SG,   (bih0[j + 18] + bhh0[j + 18]) * SSIG);
    W1.bif = pk2((bih1[j     ] + bhh1[j     ]) * SSIG, (bih1[j +  6] + bhh1[j +  6]) * SSIG);
    W1.bgo = pk2((bih1[j + 12] + bhh1[j + 12]) * SG,   (bih1[j + 18] + bhh1[j + 18]) * SSIG);

    const float2* xr = (const float2*)(x + (size_t)b * BT * 6);
    float* orow = out + (size_t)b * BT * 6 + j;

    float h0 = 0.f, c0 = 0.f, h1 = 0.f, c1 = 0.f;
    const unsigned mask = 0xffffffffu;

    // Software-pipelined: iteration t computes layer0[t] (needs h0[t-1]) and
    // layer1[t-1] (needs h0[t-1], h1[t-2]) — two independent dep chains per iter.
#pragma unroll 1
    for (int t = 0; t < BT; ++t) {
        float2 xa = __ldg(xr), xb = __ldg(xr + 1), xc = __ldg(xr + 2);
        xr += 3;
        u64 X[6] = { dup2(xa.x), dup2(xa.y), dup2(xb.x),
                     dup2(xb.y), dup2(xc.x), dup2(xc.y) };
        u64 H0d[6], H1d[6];
#pragma unroll
        for (int k = 0; k < 6; ++k) {   // src lanes base+k <= 29: never idle lanes
            H0d[k] = dup2(__shfl_sync(mask, h0, base + k));
            H1d[k] = dup2(__shfl_sync(mask, h1, base + k));
        }
        float h0n;
        lstm_cell(W0, X, H0d, c0, h0n);
        if (t > 0) {                    // uniform branch, no divergence
            float h1n;
            lstm_cell(W1, H0d, H1d, c1, h1n);
            h1 = h1n;
            if (active) orow[0] = h1n;  // output index t-1
            orow += 6;
        }
        h0 = h0n;
    }
    // epilogue: layer1 at t = BT-1
    {
        u64 H0d[6], H1d[6];
#pragma unroll
        for (int k = 0; k < 6; ++k) {
            H0d[k] = dup2(__shfl_sync(mask, h0, base + k));
            H1d[k] = dup2(__shfl_sync(mask, h1, base + k));
        }
        float h1n;
        lstm_cell(W1, H0d, H1d, c1, h1n);
        if (active) orow[0] = h1n;
    }
}

extern "C" void kernel_launch(void* const* d_in, const int* in_sizes, int n_in,
                              void* d_out, int out_size)
{
    const float* x    = (const float*)d_in[0];
    const float* wih0 = (const float*)d_in[1];
    const float* whh0 = (const float*)d_in[2];
    const float* bih0 = (const float*)d_in[3];
    const float* bhh0 = (const float*)d_in[4];
    const float* wih1 = (const float*)d_in[5];
    const float* whh1 = (const float*)d_in[6];
    const float* bih1 = (const float*)d_in[7];
    const float* bhh1 = (const float*)d_in[8];
    float* out = (float*)d_out;

    const int warps_needed = (NB + 4) / 5;          // 820 warps (5 elems/warp)
    const int cta = 64;                              // 2 warps/CTA -> 410 CTAs, even SM spread
    const int grid = (warps_needed + 1) / 2;
    lstm2_kernel<<<grid, cta>>>(x, wih0, whh0, bih0, bhh0,
                                wih1, whh1, bih1, bhh1, out);
}

// round 4
// speedup vs baseline: 1.1082x; 1.1082x over previous
#include <cuda_runtime.h>
#include <cstdint>

#define BT 1024
#define NB 4096

typedef unsigned long long u64;

__device__ __forceinline__ u64 pk2(float lo, float hi) {
    u64 r; asm("mov.b64 %0, {%1,%2};" : "=l"(r) : "f"(lo), "f"(hi)); return r;
}
__device__ __forceinline__ u64 dup2(float v) { return pk2(v, v); }
__device__ __forceinline__ void unpk2(u64 p, float& lo, float& hi) {
    asm("mov.b64 {%0,%1}, %2;" : "=f"(lo), "=f"(hi) : "l"(p));
}
__device__ __forceinline__ u64 ffma2(u64 a, u64 b, u64 c) {
    u64 d; asm("fma.rn.f32x2 %0, %1, %2, %3;" : "=l"(d) : "l"(a), "l"(b), "l"(c)); return d;
}
__device__ __forceinline__ u64 fmul2(u64 a, u64 b) {
    u64 d; asm("mul.rn.f32x2 %0, %1, %2;" : "=l"(d) : "l"(a), "l"(b)); return d;
}
__device__ __forceinline__ u64 fadd2(u64 a, u64 b) {
    u64 d; asm("add.rn.f32x2 %0, %1, %2;" : "=l"(d) : "l"(a), "l"(b)); return d;
}
__device__ __forceinline__ float ex2f(float x) {
    float y; asm("ex2.approx.f32 %0, %1;" : "=f"(y) : "f"(x)); return y;
}
__device__ __forceinline__ float rcpf(float x) {
    float y; asm("rcp.approx.f32 %0, %1;" : "=f"(y) : "f"(x)); return y;
}

// Per-thread packed weights for ONE LSTM cell (thread owns hidden unit j of one layer).
// wif[k] = (Wi[j][k]*-log2e, Wf[j][k]*-log2e), wgo[k] = (Wg[j][k]*2log2e, Wo[j][k]*-log2e)
// k=0..5: input-part, k=6..11: hidden-part. Biases pre-folded the same way.
struct LW {
    u64 wif[12];
    u64 wgo[12];
    u64 bif, bgo;
};

// Fused-activation LSTM cell (5 EX2 + 3 RCP):
//   i*g = (Eg-1)*rcp((Eg+1)(Ei+1));  f*c = c*rcp(Ef+1)
//   h   = (Ec-1)*rcp((Ec+1)(Eo+1)),  Ec = ex2(min(2log2e*c, 100))
// Matvec split into 4 independent 3-FFMA2 chains per gate-pair (short dep path).
__device__ __forceinline__ void lstm_cell(const LW& w, const u64* A, const u64* Bv,
                                          float c, float& cn, float& hn)
{
    u64 p0 = ffma2(w.wif[0], A[0], w.bif);
    p0 = ffma2(w.wif[1], A[1], p0);
    p0 = ffma2(w.wif[2], A[2], p0);
    u64 p1 = fmul2(w.wif[3], A[3]);
    p1 = ffma2(w.wif[4], A[4], p1);
    p1 = ffma2(w.wif[5], A[5], p1);
    u64 p2 = fmul2(w.wif[6], Bv[0]);
    p2 = ffma2(w.wif[7], Bv[1], p2);
    p2 = ffma2(w.wif[8], Bv[2], p2);
    u64 p3 = fmul2(w.wif[9], Bv[3]);
    p3 = ffma2(w.wif[10], Bv[4], p3);
    p3 = ffma2(w.wif[11], Bv[5], p3);
    u64 aif = fadd2(fadd2(p0, p1), fadd2(p2, p3));

    u64 q0 = ffma2(w.wgo[0], A[0], w.bgo);
    q0 = ffma2(w.wgo[1], A[1], q0);
    q0 = ffma2(w.wgo[2], A[2], q0);
    u64 q1 = fmul2(w.wgo[3], A[3]);
    q1 = ffma2(w.wgo[4], A[4], q1);
    q1 = ffma2(w.wgo[5], A[5], q1);
    u64 q2 = fmul2(w.wgo[6], Bv[0]);
    q2 = ffma2(w.wgo[7], Bv[1], q2);
    q2 = ffma2(w.wgo[8], Bv[2], q2);
    u64 q3 = fmul2(w.wgo[9], Bv[3]);
    q3 = ffma2(w.wgo[10], Bv[4], q3);
    q3 = ffma2(w.wgo[11], Bv[5], q3);
    u64 ago = fadd2(fadd2(q0, q1), fadd2(q2, q3));

    float zi, zf, zg, zo;
    unpk2(aif, zi, zf);
    unpk2(ago, zg, zo);
    float Ei = ex2f(zi), Ef = ex2f(zf), Eg = ex2f(zg), Eo = ex2f(zo);
    float ig = (Eg - 1.0f) * rcpf((Eg + 1.0f) * (Ei + 1.0f));
    cn = fmaf(c, rcpf(Ef + 1.0f), ig);
    float zc = fminf(cn * 2.8853900817779268f, 100.0f);
    float Ec = ex2f(zc);
    hn = (Ec - 1.0f) * rcpf((Ec + 1.0f) * (Eo + 1.0f));
}

// Layout: 12 lanes per batch element (lanes 0-5: layer0 units, 6-11: layer1 units),
// 2 elements per warp (lanes 0-23), lanes 24-31 retire immediately.
// Software pipeline: iter t -> layer0 lanes produce h0[t], layer1 lanes produce h1[t-1].
__global__ void __launch_bounds__(64)
lstm2_kernel(const float* __restrict__ x,
             const float* __restrict__ wih0, const float* __restrict__ whh0,
             const float* __restrict__ bih0, const float* __restrict__ bhh0,
             const float* __restrict__ wih1, const float* __restrict__ whh1,
             const float* __restrict__ bih1, const float* __restrict__ bhh1,
             float* __restrict__ out)
{
    const int lane = threadIdx.x & 31;
    if (lane >= 24) return;
    const unsigned mask = 0x00ffffffu;

    const int warp = (blockIdx.x << 1) | (threadIdx.x >> 5);
    const int e  = lane / 12;          // element slot in warp (0,1)
    const int r  = lane % 12;
    const bool is_l1 = (r >= 6);       // layer of this lane
    const int j  = r % 6;              // hidden unit
    const int b  = warp * 2 + e;       // batch element (exact: 2048 warps * 2 = 4096)
    const int mybase = lane - j;       // first lane of my 6-lane layer group
    const int abase  = is_l1 ? mybase - 6 : mybase;  // layer1 input = layer0 group's h

    const float SSIG = -1.4426950408889634f;   // -log2(e)
    const float SG   =  2.8853900817779268f;   //  2*log2(e)

    const float* Wih = is_l1 ? wih1 : wih0;
    const float* Whh = is_l1 ? whh1 : whh0;
    const float* Bih = is_l1 ? bih1 : bih0;
    const float* Bhh = is_l1 ? bhh1 : bhh0;

    LW W;
#pragma unroll
    for (int k = 0; k < 12; ++k) {
        const float* Ws = (k < 6) ? Wih : Whh;
        const int kk = (k < 6) ? k : k - 6;
        W.wif[k] = pk2(Ws[(j     ) * 6 + kk] * SSIG, Ws[(j +  6) * 6 + kk] * SSIG);
        W.wgo[k] = pk2(Ws[(j + 12) * 6 + kk] * SG,   Ws[(j + 18) * 6 + kk] * SSIG);
    }
    W.bif = pk2((Bih[j     ] + Bhh[j     ]) * SSIG, (Bih[j +  6] + Bhh[j +  6]) * SSIG);
    W.bgo = pk2((Bih[j + 12] + Bhh[j + 12]) * SG,   (Bih[j + 18] + Bhh[j + 18]) * SSIG);

    // ---- x register prefetch, depth 2 (layer0 lanes only) ----
    const float2* xp2 = (const float2*)(x + (size_t)b * BT * 6);
    float Xc[6], Xn[6], Xp[6];
#pragma unroll
    for (int k = 0; k < 6; ++k) { Xc[k] = 0.f; Xn[k] = 0.f; Xp[k] = 0.f; }
    if (!is_l1) {
        float2 a0 = __ldg(xp2 + 0), a1 = __ldg(xp2 + 1), a2 = __ldg(xp2 + 2);
        Xc[0]=a0.x; Xc[1]=a0.y; Xc[2]=a1.x; Xc[3]=a1.y; Xc[4]=a2.x; Xc[5]=a2.y;
        float2 b0 = __ldg(xp2 + 3), b1 = __ldg(xp2 + 4), b2 = __ldg(xp2 + 5);
        Xn[0]=b0.x; Xn[1]=b0.y; Xn[2]=b1.x; Xn[3]=b1.y; Xn[4]=b2.x; Xn[5]=b2.y;
    }
    xp2 += 6;

    float* orow = out + (size_t)b * BT * 6 + j;
    float h = 0.f, c = 0.f;

#pragma unroll 1
    for (int t = 0; t <= BT; ++t) {
        // prefetch x[t+2] (recurrence-independent: ~2 iterations of latency slack)
        if (!is_l1 && t < BT - 2) {
            float2 a0 = __ldg(xp2 + 0), a1 = __ldg(xp2 + 1), a2 = __ldg(xp2 + 2);
            Xp[0]=a0.x; Xp[1]=a0.y; Xp[2]=a1.x; Xp[3]=a1.y; Xp[4]=a2.x; Xp[5]=a2.y;
        }
        xp2 += 3;

        // exchange previous hidden states
        float SA[6], SB[6];
#pragma unroll
        for (int k = 0; k < 6; ++k) {
            SA[k] = __shfl_sync(mask, h, abase  + k);   // layer1's input = h0[t-1]
            SB[k] = __shfl_sync(mask, h, mybase + k);   // own recurrent h
        }

        u64 A[6], B[6];
#pragma unroll
        for (int k = 0; k < 6; ++k) {
            A[k] = dup2(is_l1 ? SA[k] : Xc[k]);
            B[k] = dup2(SB[k]);
        }

        float cn, hn;
        lstm_cell(W, A, B, c, cn, hn);

        // layer0 valid for t < BT (produces h0[t]); layer1 valid for t > 0 (produces h1[t-1])
        const bool commit = is_l1 ? (t > 0) : (t < BT);
        if (commit) { c = cn; h = hn; }

        if (is_l1 && t > 0) { orow[0] = hn; orow += 6; }

        if (!is_l1) {
#pragma unroll
            for (int k = 0; k < 6; ++k) { Xc[k] = Xn[k]; Xn[k] = Xp[k]; }
        }
    }
}

extern "C" void kernel_launch(void* const* d_in, const int* in_sizes, int n_in,
                              void* d_out, int out_size)
{
    const float* x    = (const float*)d_in[0];
    const float* wih0 = (const float*)d_in[1];
    const float* whh0 = (const float*)d_in[2];
    const float* bih0 = (const float*)d_in[3];
    const float* bhh0 = (const float*)d_in[4];
    const float* wih1 = (const float*)d_in[5];
    const float* whh1 = (const float*)d_in[6];
    const float* bih1 = (const float*)d_in[7];
    const float* bhh1 = (const float*)d_in[8];
    float* out = (float*)d_out;

    // 4096 elements * 12 lanes = 2048 warps; 2 warps/CTA -> 1024 CTAs (~7/SM, even)
    lstm2_kernel<<<1024, 64>>>(x, wih0, whh0, bih0, bhh0,
                               wih1, whh1, bih1, bhh1, out);
}

// round 5
// speedup vs baseline: 1.4660x; 1.3229x over previous
#include <cuda_runtime.h>
#include <cstdint>

#define BT 1024
#define NB 4096

typedef unsigned long long u64;

__device__ __forceinline__ u64 pk2(float lo, float hi) {
    u64 r; asm("mov.b64 %0, {%1,%2};" : "=l"(r) : "f"(lo), "f"(hi)); return r;
}
__device__ __forceinline__ void unpk2(u64 p, float& lo, float& hi) {
    asm("mov.b64 {%0,%1}, %2;" : "=f"(lo), "=f"(hi) : "l"(p));
}
__device__ __forceinline__ u64 ffma2(u64 a, u64 b, u64 c) {
    u64 d; asm("fma.rn.f32x2 %0, %1, %2, %3;" : "=l"(d) : "l"(a), "l"(b), "l"(c)); return d;
}
__device__ __forceinline__ u64 fmul2(u64 a, u64 b) {
    u64 d; asm("mul.rn.f32x2 %0, %1, %2;" : "=l"(d) : "l"(a), "l"(b)); return d;
}
__device__ __forceinline__ u64 fadd2(u64 a, u64 b) {
    u64 d; asm("add.rn.f32x2 %0, %1, %2;" : "=l"(d) : "l"(a), "l"(b)); return d;
}
__device__ __forceinline__ float ex2f(float x) {
    float y; asm("ex2.approx.f32 %0, %1;" : "=f"(y) : "f"(x)); return y;
}
__device__ __forceinline__ float rcpf(float x) {
    float y; asm("rcp.approx.f32 %0, %1;" : "=f"(y) : "f"(x)); return y;
}

// Reduction-dim f32x2 packing: FFMA2 multiplies (w[2m], w[2m+1]) by (v[2m], v[2m+1]);
// each gate accumulates (even_sum, odd_sum), combined by one horizontal add at the end.
// Gate scales pre-folded into weights: i/f/o * -log2e, g * 2log2e.
// Fused activations (5 EX2 + 3 RCP per cell):
//   i*g = (Eg-1)*rcp((Eg+1)(Ei+1));  f*c = c*rcp(Ef+1)
//   h   = (Ec-1)*rcp((Ec+1)(Eo+1)),  Ec = ex2(min(2log2e*c, 100))

__global__ void __launch_bounds__(64)
lstm2_kernel(const float* __restrict__ x,
             const float* __restrict__ wih0, const float* __restrict__ whh0,
             const float* __restrict__ bih0, const float* __restrict__ bhh0,
             const float* __restrict__ wih1, const float* __restrict__ whh1,
             const float* __restrict__ bih1, const float* __restrict__ bhh1,
             float* __restrict__ out)
{
    const int lane = threadIdx.x & 31;
    if (lane >= 24) return;                 // 12 lanes per element, 2 elements/warp
    const unsigned mask = 0x00ffffffu;

    const int warp = (blockIdx.x << 1) | (threadIdx.x >> 5);
    const int e  = lane / 12;
    const int r  = lane % 12;
    const bool is_l1 = (r >= 6);            // lanes 0-5: layer0, 6-11: layer1
    const int j  = r % 6;                   // hidden unit
    const int b  = warp * 2 + e;            // 2048 warps * 2 = 4096 exact
    const int mybase = lane - j;
    const int abase  = is_l1 ? mybase - 6 : mybase;

    const float SSIG = -1.4426950408889634f;   // -log2(e)
    const float SGc  =  2.8853900817779268f;   //  2*log2(e)

    const float* Wih = is_l1 ? wih1 : wih0;
    const float* Whh = is_l1 ? whh1 : whh0;
    const float* Bih = is_l1 ? bih1 : bih0;
    const float* Bhh = is_l1 ? bhh1 : bhh0;

    u64 WA[4][3], WB[4][3], BA[4];          // per-gate reduction-packed weights
#pragma unroll
    for (int q = 0; q < 4; ++q) {           // q: 0=i 1=f 2=g 3=o (PyTorch row order)
        const int row = j + 6 * q;
        const float s = (q == 2) ? SGc : SSIG;
#pragma unroll
        for (int m = 0; m < 3; ++m) {
            WA[q][m] = pk2(Wih[row * 6 + 2 * m] * s, Wih[row * 6 + 2 * m + 1] * s);
            WB[q][m] = pk2(Whh[row * 6 + 2 * m] * s, Whh[row * 6 + 2 * m + 1] * s);
        }
        BA[q] = pk2((Bih[row] + Bhh[row]) * s, 0.0f);
    }

    // x rows are 24B = 3 u64, 8B-aligned: load pre-packed pairs directly.
    const u64* xrow = (const u64*)(x + (size_t)b * BT * 6);
    u64 X0[3], X1[3], X2[3], P[3];
#pragma unroll
    for (int m = 0; m < 3; ++m) {
        P[m]  = __ldg(xrow + m);            // t=0 (peel)
        X0[m] = __ldg(xrow + 3 + m);        // t=1
        X1[m] = __ldg(xrow + 6 + m);        // t=2
        X2[m] = __ldg(xrow + 9 + m);        // t=3
    }

    float h = 0.f, c = 0.f;
    float* orow = out + (size_t)b * BT * 6 + j;

    // One cell step given packed inputs A (x or h0) and recurrent pairs Bp.
    auto cell = [&](const u64 A[3], const u64 Bp[3], float cin, float& cn, float& hn) {
        float z[4];
#pragma unroll
        for (int q = 0; q < 4; ++q) {
            u64 a = ffma2(WA[q][0], A[0], BA[q]);
            a = ffma2(WA[q][1], A[1], a);
            a = ffma2(WA[q][2], A[2], a);
            u64 bb = fmul2(WB[q][0], Bp[0]);
            bb = ffma2(WB[q][1], Bp[1], bb);
            bb = ffma2(WB[q][2], Bp[2], bb);
            a = fadd2(a, bb);
            float lo, hi; unpk2(a, lo, hi);
            z[q] = lo + hi;
        }
        float Ei = ex2f(z[0]), Ef = ex2f(z[1]), Eg = ex2f(z[2]), Eo = ex2f(z[3]);
        float ig = (Eg - 1.0f) * rcpf((Eg + 1.0f) * (Ei + 1.0f));
        cn = fmaf(cin, rcpf(Ef + 1.0f), ig);
        float zc = fminf(cn * SGc, 100.0f);
        float Ec = ex2f(zc);
        hn = (Ec - 1.0f) * rcpf((Ec + 1.0f) * (Eo + 1.0f));
    };

    auto gather = [&](u64 A[3], u64 Bp[3], const u64* Xu) {
        float sa[6], sb[6];
#pragma unroll
        for (int m = 0; m < 6; ++m) sa[m] = __shfl_sync(mask, h, abase + m);
#pragma unroll
        for (int m = 0; m < 6; ++m) sb[m] = __shfl_sync(mask, h, mybase + m);
#pragma unroll
        for (int m = 0; m < 3; ++m) {
            u64 sap = pk2(sa[2 * m], sa[2 * m + 1]);   // pack from 2 shfl dests: ~free
            A[m]  = is_l1 ? sap : Xu[m];
            Bp[m] = pk2(sb[2 * m], sb[2 * m + 1]);
        }
    };

    // ---- peel t=0: layer0 commits h0[0]; layer1 result discarded ----
    {
        u64 A[3], Bp[3];
        gather(A, Bp, P);
        float cn, hn;
        cell(A, Bp, c, cn, hn);
        if (!is_l1) { h = hn; c = cn; }
    }

    // ---- steady state t = 1..1023 (= 341*3): no conditionals in body ----
    // iter t: layer0 lanes produce h0[t], layer1 lanes produce h1[t-1] (stored).
    auto body = [&](u64* Xu, int t) {
        u64 A[3], Bp[3];
        gather(A, Bp, Xu);
        const int tf = (t + 3 < BT) ? t + 3 : BT - 1;   // prefetch distance 3
#pragma unroll
        for (int m = 0; m < 3; ++m) Xu[m] = __ldg(xrow + tf * 3 + m);
        float cn, hn;
        cell(A, Bp, c, cn, hn);
        h = hn; c = cn;
        if (is_l1) orow[0] = hn;
        orow += 6;
    };

    int t = 1;
#pragma unroll 1
    for (int g = 0; g < 341; ++g) {
        body(X0, t);
        body(X1, t + 1);
        body(X2, t + 2);
        t += 3;
    }

    // ---- epilogue t=1024: layer1 computes & stores h1[1023] ----
    {
        u64 A[3], Bp[3];
        gather(A, Bp, P);                    // l0 lanes compute garbage (not committed)
        float cn, hn;
        cell(A, Bp, c, cn, hn);
        if (is_l1) orow[0] = hn;
    }
}

extern "C" void kernel_launch(void* const* d_in, const int* in_sizes, int n_in,
                              void* d_out, int out_size)
{
    const float* x    = (const float*)d_in[0];
    const float* wih0 = (const float*)d_in[1];
    const float* whh0 = (const float*)d_in[2];
    const float* bih0 = (const float*)d_in[3];
    const float* bhh0 = (const float*)d_in[4];
    const float* wih1 = (const float*)d_in[5];
    const float* whh1 = (const float*)d_in[6];
    const float* bih1 = (const float*)d_in[7];
    const float* bhh1 = (const float*)d_in[8];
    float* out = (float*)d_out;

    // 4096 elements * 12 lanes = 2048 warps; 2 warps/CTA -> 1024 CTAs
    lstm2_kernel<<<1024, 64>>>(x, wih0, whh0, bih0, bhh0,
                               wih1, whh1, bih1, bhh1, out);
}

// round 8
// speedup vs baseline: 1.4662x; 1.0002x over previous
#include <cuda_runtime.h>
#include <cstdint>

#define BT 1024
#define NB 4096

typedef unsigned long long u64;

__device__ __forceinline__ u64 pk2(float lo, float hi) {
    u64 r; asm("mov.b64 %0, {%1,%2};" : "=l"(r) : "f"(lo), "f"(hi)); return r;
}
__device__ __forceinline__ void unpk2(u64 p, float& lo, float& hi) {
    asm("mov.b64 {%0,%1}, %2;" : "=f"(lo), "=f"(hi) : "l"(p));
}
__device__ __forceinline__ u64 ffma2(u64 a, u64 b, u64 c) {
    u64 d; asm("fma.rn.f32x2 %0, %1, %2, %3;" : "=l"(d) : "l"(a), "l"(b), "l"(c)); return d;
}
__device__ __forceinline__ u64 fmul2(u64 a, u64 b) {
    u64 d; asm("mul.rn.f32x2 %0, %1, %2;" : "=l"(d) : "l"(a), "l"(b)); return d;
}
__device__ __forceinline__ u64 fadd2(u64 a, u64 b) {
    u64 d; asm("add.rn.f32x2 %0, %1, %2;" : "=l"(d) : "l"(a), "l"(b)); return d;
}
__device__ __forceinline__ float ex2f(float x) {
    float y; asm("ex2.approx.f32 %0, %1;" : "=f"(y) : "f"(x)); return y;
}
__device__ __forceinline__ float rcpf(float x) {
    float y; asm("rcp.approx.f32 %0, %1;" : "=f"(y) : "f"(x)); return y;
}

// Reduction-dim f32x2 packed weights, gate scales pre-folded (i/f/o: -log2e, g: +2log2e).
struct CellW { u64 WA[4][3], WB[4][3], BA[4]; };

// Fused-activation LSTM cell (5 EX2 + 3 RCP):
//   i*g = (Eg-1)*rcp((Eg+1)(Ei+1));  f*c = c*rcp(Ef+1)
//   h   = (Ec-1)*rcp((Ec+1)(Eo+1)),  Ec = ex2(min(2log2e*c, 100))
__device__ __forceinline__ void cell(const CellW& w, const u64* A, const u64* Bp,
                                     float cin, float& cn, float& hn)
{
    float z[4];
#pragma unroll
    for (int q = 0; q < 4; ++q) {
        u64 a = ffma2(w.WA[q][0], A[0], w.BA[q]);
        a = ffma2(w.WA[q][1], A[1], a);
        a = ffma2(w.WA[q][2], A[2], a);
        u64 bb = fmul2(w.WB[q][0], Bp[0]);
        bb = ffma2(w.WB[q][1], Bp[1], bb);
        bb = ffma2(w.WB[q][2], Bp[2], bb);
        a = fadd2(a, bb);
        float lo, hi; unpk2(a, lo, hi);
        z[q] = lo + hi;
    }
    float Ei = ex2f(z[0]), Ef = ex2f(z[1]), Eg = ex2f(z[2]), Eo = ex2f(z[3]);
    float ig = (Eg - 1.0f) * rcpf((Eg + 1.0f) * (Ei + 1.0f));
    cn = fmaf(cin, rcpf(Ef + 1.0f), ig);
    float zc = fminf(cn * 2.8853900817779268f, 100.0f);
    float Ec = ex2f(zc);
    hn = (Ec - 1.0f) * rcpf((Ec + 1.0f) * (Eo + 1.0f));
}

// smem per element (320B, padded for bank-conflict-free across the 2 elems/warp):
//   A region [0,192): 4 slots*48B; slot s: [0,24)=x[t], [24,48)=h0[t-1]  (A input data)
//   B region [192,288): 2 slots*48B; slot s: [0,24)=h0, [24,48)=h1      (recurrent data)
// Software pipeline body t: layer0 lanes -> h0[t], layer1 lanes -> h1[t-1] (stored).
// x staging: body t LDGs x[t+5] (1 u64/stager lane), STSs x[t+3] (LDG'd 2 bodies ago).

#define BODY(TP,BR,BW,AH,XS,Q,LDI,STI,DOLDG,DOSTSX,DOSTG) do {               \
    u64 A_[3], B_[3];                                                        \
    A_[0] = *(const u64*)(a_base  + (TP)*48 + 0);                            \
    A_[1] = *(const u64*)(a_base  + (TP)*48 + 8);                            \
    A_[2] = *(const u64*)(a_base  + (TP)*48 + 16);                           \
    B_[0] = *(const u64*)(bb_base + (BR)*48 + 0);                            \
    B_[1] = *(const u64*)(bb_base + (BR)*48 + 8);                            \
    B_[2] = *(const u64*)(bb_base + (BR)*48 + 16);                           \
    float cn_, hn_;                                                          \
    cell(W, A_, B_, c, cn_, hn_);                                            \
    c = cn_; h = hn_;                                                        \
    if ((DOSTG) && is_l1) og_run[(STI)] = hn_;                               \
    *(float*)(hst_base + (BW)*48) = h;                                       \
    if (!is_l1) *(float*)(h0st_base + (AH)*48) = h;                          \
    if ((DOSTSX) && stager) *(u64*)(xst_base + (XS)*48) = xq[(Q)];           \
    if ((DOLDG)  && stager) xq[(Q)] = __ldg(xg_run + (LDI));                 \
    __syncwarp(0x00ffffffu);                                                 \
} while (0)

__global__ void __launch_bounds__(64)
lstm2_kernel(const float* __restrict__ x,
             const float* __restrict__ wih0, const float* __restrict__ whh0,
             const float* __restrict__ bih0, const float* __restrict__ bhh0,
             const float* __restrict__ wih1, const float* __restrict__ whh1,
             const float* __restrict__ bih1, const float* __restrict__ bhh1,
             float* __restrict__ out)
{
    __shared__ __align__(16) char sm[4 * 320];

    const int lane = threadIdx.x & 31;
    if (lane >= 24) return;                       // 12 lanes/element, 2 elements/warp
    const int e = lane / 12;
    const int r = lane % 12;
    const bool is_l1 = (r >= 6);                  // lanes 0-5: layer0, 6-11: layer1
    const int j = r % 6;                          // hidden unit
    const int warp = (blockIdx.x << 1) | (threadIdx.x >> 5);
    const int b = warp * 2 + e;                   // 2048 warps * 2 = 4096 exact
    const bool stager = (!is_l1) && (j < 3);      // 3 lanes stage x (1 u64 each)

    char* elem      = sm + ((threadIdx.x >> 5) * 2 + e) * 320;
    char* a_base    = elem + (is_l1 ? 24 : 0);            // + TP*48 + m*8
    char* bb_base   = elem + 192 + (is_l1 ? 24 : 0);      // + BR*48 + m*8
    char* hst_base  = elem + 192 + r * 4;                 // + BW*48
    char* h0st_base = elem + 24 + j * 4;                  // + AH*48 (layer0 only)
    char* xst_base  = elem + j * 8;                       // + XS*48 (stagers only)

    const float SSIG = -1.4426950408889634f;   // -log2(e)
    const float SGc  =  2.8853900817779268f;   //  2*log2(e)

    const float* Wih = is_l1 ? wih1 : wih0;
    const float* Whh = is_l1 ? whh1 : whh0;
    const float* Bih = is_l1 ? bih1 : bih0;
    const float* Bhh = is_l1 ? bhh1 : bhh0;

    CellW W;
#pragma unroll
    for (int q = 0; q < 4; ++q) {              // q: 0=i 1=f 2=g 3=o
        const int row = j + 6 * q;
        const float s = (q == 2) ? SGc : SSIG;
#pragma unroll
        for (int m = 0; m < 3; ++m) {
            W.WA[q][m] = pk2(Wih[row * 6 + 2 * m] * s, Wih[row * 6 + 2 * m + 1] * s);
            W.WB[q][m] = pk2(Whh[row * 6 + 2 * m] * s, Whh[row * 6 + 2 * m + 1] * s);
        }
        W.BA[q] = pk2((Bih[row] + Bhh[row]) * s, 0.0f);
    }

    const u64* xg_run = (const u64*)(x + (size_t)b * (BT * 6)) + j;  // u64 idx t*3+j
    float* og_run = out + (size_t)b * (BT * 6) + j;
    float h = 0.f, c = 0.f;
    u64 xq[2] = {0ull, 0ull};

    // ---- prologue: zero init slots, stage x[0..2], prime xq with x[3],x[4] ----
    *(float*)(hst_base + 48) = 0.f;                 // B slot1 = h[-1] = 0
    if (!is_l1) *(float*)(h0st_base + 0) = 0.f;     // A slot0 h0 (body0 l1, discarded)
    if (stager) {
        *(u64*)(xst_base + 0 * 48) = __ldg(xg_run + 0);
        *(u64*)(xst_base + 1 * 48) = __ldg(xg_run + 3);
        *(u64*)(xst_base + 2 * 48) = __ldg(xg_run + 6);
        xq[0] = __ldg(xg_run + 9);    // x[3]
        xq[1] = __ldg(xg_run + 12);   // x[4]
    }
    __syncwarp(0x00ffffffu);

    // ---- peel t=0: commit layer0 only (layer1 result discarded), no STG ----
    {
        u64 A_[3], B_[3];
        A_[0] = *(const u64*)(a_base + 0);
        A_[1] = *(const u64*)(a_base + 8);
        A_[2] = *(const u64*)(a_base + 16);
        B_[0] = *(const u64*)(bb_base + 48 + 0);
        B_[1] = *(const u64*)(bb_base + 48 + 8);
        B_[2] = *(const u64*)(bb_base + 48 + 16);
        float cn_, hn_;
        cell(W, A_, B_, c, cn_, hn_);
        if (!is_l1) { c = cn_; h = hn_; }
        *(float*)(hst_base + 0) = h;                       // BW=0
        if (!is_l1) *(float*)(h0st_base + 48) = h;         // AH=1
        if (stager) {
            *(u64*)(xst_base + 3 * 48) = xq[0];            // x[3] -> slot 3
            xq[0] = __ldg(xg_run + 15);                    // x[5]
        }
        __syncwarp(0x00ffffffu);
    }
    xg_run += 3;   // t_base = 1

    // ---- main: t = 1..1016 (254 groups of 4); all immediates compile-time ----
#pragma unroll 1
    for (int g = 0; g < 254; ++g) {
        //   TP BR BW AH XS Q  LDI STI
        BODY(1, 0, 1, 2, 0, 1, 15,  0, true, true, true);   // t%4==1
        BODY(2, 1, 0, 3, 1, 0, 18,  6, true, true, true);   // t%4==2
        BODY(3, 0, 1, 0, 2, 1, 21, 12, true, true, true);   // t%4==3
        BODY(0, 1, 0, 1, 3, 0, 24, 18, true, true, true);   // t%4==0
        xg_run += 12;
        og_run += 24;
    }

    // ---- tail: t = 1017..1023 (xg_run at t_base=1017, og_run at out[1016*6]) ----
    BODY(1, 0, 1, 2, 0, 1, 15,  0, true,  true,  true);   // t=1017: LDG x[1022], STS x[1020]
    BODY(2, 1, 0, 3, 1, 0, 18,  6, true,  true,  true);   // t=1018: LDG x[1023], STS x[1021]
    BODY(3, 0, 1, 0, 2, 1,  0, 12, false, true,  true);   // t=1019: STS x[1022]
    BODY(0, 1, 0, 1, 3, 0,  0, 18, false, true,  true);   // t=1020: STS x[1023]
    BODY(1, 0, 1, 2, 0, 1,  0, 24, false, false, true);   // t=1021
    BODY(2, 1, 0, 3, 1, 0,  0, 30, false, false, true);   // t=1022
    BODY(3, 0, 1, 0, 2, 1,  0, 36, false, false, true);   // t=1023

    // ---- epilogue t=1024: layer1 computes & stores h1[1023] ----
    {
        u64 A_[3], B_[3];
        A_[0] = *(const u64*)(a_base + 0);                 // slot0: h0[1023] for l1
        A_[1] = *(const u64*)(a_base + 8);
        A_[2] = *(const u64*)(a_base + 16);
        B_[0] = *(const u64*)(bb_base + 48 + 0);           // slot1: h[1023]
        B_[1] = *(const u64*)(bb_base + 48 + 8);
        B_[2] = *(const u64*)(bb_base + 48 + 16);
        float cn_, hn_;
        cell(W, A_, B_, c, cn_, hn_);
        if (is_l1) og_run[42] = hn_;                       // out[1023*6 + j]
    }
}

extern "C" void kernel_launch(void* const* d_in, const int* in_sizes, int n_in,
                              void* d_out, int out_size)
{
    const float* x    = (const float*)d_in[0];
    const float* wih0 = (const float*)d_in[1];
    const float* whh0 = (const float*)d_in[2];
    const float* bih0 = (const float*)d_in[3];
    const float* bhh0 = (const float*)d_in[4];
    const float* wih1 = (const float*)d_in[5];
    const float* whh1 = (const float*)d_in[6];
    const float* bih1 = (const float*)d_in[7];
    const float* bhh1 = (const float*)d_in[8];
    float* out = (float*)d_out;

    // 4096 elements * 12 lanes = 2048 warps; 2 warps/CTA -> 1024 CTAs
    lstm2_kernel<<<1024, 64>>>(x, wih0, whh0, bih0, bhh0,
                               wih1, whh1, bih1, bhh1, out);
}